// round 11
// baseline (speedup 1.0000x reference)
#include <cuda_runtime.h>
#include <math.h>

// Scratch: one full-size intermediate buffer (B*M*N floats = 134 MB).
#define SCRATCH_ELEMS (2ull * 4096ull * 4096ull)
__device__ float g_scratch[SCRATCH_ELEMS];

// Problem shape fixed: B=2, M=N=4096. Real-packed FFT length = 2048.
#define NN 4096
#define HH 2048

// ---- packed f32x2 complex add/sub (sm_103a) ----
__device__ __forceinline__ float2 cadd(float2 a, float2 b){
    unsigned long long ua, ub, ur;
    asm("mov.b64 %0, {%1,%2};" : "=l"(ua) : "f"(a.x), "f"(a.y));
    asm("mov.b64 %0, {%1,%2};" : "=l"(ub) : "f"(b.x), "f"(b.y));
    asm("add.rn.f32x2 %0, %1, %2;" : "=l"(ur) : "l"(ua), "l"(ub));
    float2 r;
    asm("mov.b64 {%0,%1}, %2;" : "=f"(r.x), "=f"(r.y) : "l"(ur));
    return r;
}
__device__ __forceinline__ float2 csub(float2 a, float2 b){
    unsigned long long ua, ub, ur;
    asm("mov.b64 %0, {%1,%2};" : "=l"(ua) : "f"(a.x), "f"(a.y));
    asm("mov.b64 %0, {%1,%2};" : "=l"(ub) : "f"(b.x), "f"(b.y));
    asm("sub.rn.f32x2 %0, %1, %2;" : "=l"(ur) : "l"(ua), "l"(ub));
    float2 r;
    asm("mov.b64 {%0,%1}, %2;" : "=f"(r.x), "=f"(r.y) : "l"(ur));
    return r;
}
__device__ __forceinline__ float2 cmul(float2 a, float2 b){
    return make_float2(fmaf(a.x, b.x, -a.y*b.y), fmaf(a.x, b.y, a.y*b.x));
}
__device__ __forceinline__ float2 mulip(float2 a){ return make_float2(-a.y, a.x); }  // * (+i)

// Pad one float2 every 16.
#define PIDX(a) ((a) + ((a) >> 4))
#define PBUF (HH + (HH >> 4))   // 2176 float2

// ---- 16-point inverse DFT in registers ----
__device__ __forceinline__ void r16_bfly(float2 g[16]) {
    const float C8 = 0.70710678118654752f;
    const float2 W1 = make_float2( 0.92387953251128674f,  0.38268343236508978f);
    const float2 W2 = make_float2( C8,  C8);
    const float2 W3 = make_float2( 0.38268343236508978f,  0.92387953251128674f);
    const float2 W6 = make_float2(-C8,  C8);
    const float2 W9 = make_float2(-0.92387953251128674f, -0.38268343236508978f);
    float2 c[16];
#pragma unroll
    for (int t0 = 0; t0 < 4; t0++) {
        float2 x0 = g[t0], x1 = g[t0+4], x2 = g[t0+8], x3 = g[t0+12];
        float2 s02 = cadd(x0,x2), d02 = csub(x0,x2);
        float2 s13 = cadd(x1,x3), d13 = csub(x1,x3);
        float2 id13 = mulip(d13);
        c[t0*4+0] = cadd(s02,s13);
        c[t0*4+1] = cadd(d02,id13);
        c[t0*4+2] = csub(s02,s13);
        c[t0*4+3] = csub(d02,id13);
    }
    c[5]  = cmul(c[5],  W1);
    c[6]  = cmul(c[6],  W2);
    c[7]  = cmul(c[7],  W3);
    c[9]  = cmul(c[9],  W2);
    c[10] = mulip(c[10]);
    c[11] = cmul(c[11], W6);
    c[13] = cmul(c[13], W3);
    c[14] = cmul(c[14], W6);
    c[15] = cmul(c[15], W9);
#pragma unroll
    for (int u0 = 0; u0 < 4; u0++) {
        float2 x0 = c[u0], x1 = c[4+u0], x2 = c[8+u0], x3 = c[12+u0];
        float2 s02 = cadd(x0,x2), d02 = csub(x0,x2);
        float2 s13 = cadd(x1,x3), d13 = csub(x1,x3);
        float2 id13 = mulip(d13);
        g[u0]    = cadd(s02,s13);
        g[u0+4]  = cadd(d02,id13);
        g[u0+8]  = csub(s02,s13);
        g[u0+12] = csub(d02,id13);
    }
}

// ---- 8-point inverse DFT in registers (a[u] -> B_u) ----
__device__ __forceinline__ void r8_bfly(float2 a[8]) {
    const float C8 = 0.70710678118654752f;
    float2 e0 = cadd(a[0],a[4]), e1 = cadd(a[1],a[5]);
    float2 e2 = cadd(a[2],a[6]), e3 = cadd(a[3],a[7]);
    float2 o0 = csub(a[0],a[4]), o1 = csub(a[1],a[5]);
    float2 o2 = csub(a[2],a[6]), o3 = csub(a[3],a[7]);
    o1 = make_float2(C8*(o1.x - o1.y),  C8*(o1.x + o1.y));
    o2 = mulip(o2);
    o3 = make_float2(-C8*(o3.x + o3.y), C8*(o3.x - o3.y));
    float2 t0 = cadd(e0,e2), t1 = csub(e0,e2);
    float2 t2 = cadd(e1,e3), t3 = csub(e1,e3);
    float2 it3 = mulip(t3);
    float2 u0 = cadd(o0,o2), u1 = csub(o0,o2);
    float2 u2 = cadd(o1,o3), u3 = csub(o1,o3);
    float2 iu3 = mulip(u3);
    a[0] = cadd(t0,t2);  a[4] = csub(t0,t2);
    a[2] = cadd(t1,it3); a[6] = csub(t1,it3);
    a[1] = cadd(u0,u2);  a[5] = csub(u0,u2);
    a[3] = cadd(u1,iu3); a[7] = csub(u1,iu3);
}

// ---------------------------------------------------------------------------
// Row FFT kernel: Makhoul pre-twiddle (expk computed on the fly, no loads)
// -> real-packed G (2048) -> radix 16/16/8 Stockham inverse FFT ->
// de-interleave epilogue. 128 thr, 1 row/CTA.
// MODE 0 = IDCT-II inverse, MODE 1 = IDXST.
// expk_k = e^{i pi k/8192}; for j = idx+128t: chain step e^{i pi/64},
// and expk[j+2048] = expk[j] * e^{i pi/4}.
// ---------------------------------------------------------------------------
template <int MODE>
__global__ __launch_bounds__(128, 4)
void dct_fft_kernel(const float* __restrict__ in,
                    const float2* __restrict__ expk,  // unused (kept for ABI)
                    float* __restrict__ out) {
    __shared__ __align__(16) float2 sX[PBUF];
    __shared__ __align__(16) float2 sY[PBUF];
    float* xs = (float*)sX;

    const int idx = threadIdx.x;
    const size_t base = (size_t)blockIdx.x * (size_t)NN;

    {
        const float4* in4 = (const float4*)(in + base);
        float4* xs4 = (float4*)xs;
#pragma unroll
        for (int i = idx; i < NN/4; i += 128) xs4[i] = in4[i];
    }
    __syncthreads();

    // Stage A: prologue + radix-16 + twiddle, write sY.
    {
        float2 g[16];
        const float2 E32 = make_float2(0.98078528040323044f, 0.19509032201612827f);   // e^{2pi i/32}
        const float2 EKS = make_float2(0.99879545620517239f, 0.04906767432741801f);   // e^{i pi/64}
        const float2 PI4 = make_float2(0.70710678118654752f, 0.70710678118654752f);   // e^{i pi/4}
        float sn, cs;
        __sincosf((float)(2.0*M_PI/4096.0) * (float)idx, &sn, &cs);
        float2 w = make_float2(cs, sn);
        __sincosf((float)(M_PI/8192.0) * (float)idx, &sn, &cs);
        float2 ek = make_float2(cs, sn);       // expk[idx]
#pragma unroll
        for (int t = 0; t < 16; t++) {
            const int j = idx + 128*t;
            float Xa0, Xb0, Xa1, Xb1;
            if (MODE == 0) {
                Xa0 = xs[j];
                Xb0 = (j == 0) ? 0.0f : xs[NN - j];
                Xa1 = xs[j + HH];
                Xb1 = xs[(j == 0) ? HH : (HH - j)];
            } else {
                Xa0 = (j == 0) ? 0.0f : xs[NN - j];
                Xb0 = (j == 0) ? 0.0f : xs[j];
                Xa1 = xs[(j == 0) ? HH : (HH - j)];
                Xb1 = xs[j + HH];
            }
            const float2 ea = ek;
            const float2 eb = cmul(ek, PI4);   // expk[j + HH]
            float2 V0 = make_float2(0.5f*(Xa0*ea.x + Xb0*ea.y),
                                    0.5f*(Xa0*ea.y - Xb0*ea.x));
            float2 V1 = make_float2(0.5f*(Xa1*eb.x + Xb1*eb.y),
                                    0.5f*(Xa1*eb.y - Xb1*eb.x));
            float2 S = cadd(V0, V1);
            float2 D = csub(V0, V1);
            float2 wd = cmul(w, D);
            g[t] = make_float2(S.x - wd.y, S.y + wd.x);
            w = cmul(w, E32);
            ek = cmul(ek, EKS);
        }
        r16_bfly(g);
        __sincosf((float)(2.0*M_PI/2048.0) * (float)idx, &sn, &cs);
        const float2 w1 = make_float2(cs, sn);
        sY[PIDX(16*idx)] = g[0];
        float2 wu = w1;
#pragma unroll
        for (int u = 1; u < 16; u++) {
            sY[PIDX(16*idx + u)] = cmul(g[u], wu);
            wu = cmul(wu, w1);
        }
    }
    __syncthreads();

    // Stage B: radix-16, S=16.
    {
        float2 g[16];
#pragma unroll
        for (int t = 0; t < 16; t++) g[t] = sY[PIDX(idx + 128*t)];
        r16_bfly(g);
        const int p = idx >> 4, j = idx & 15;
        float sn, cs;
        __sincosf((float)(2.0*M_PI/128.0) * (float)p, &sn, &cs);
        const float2 w1 = make_float2(cs, sn);
        const int ob = j + 256*p;
        sX[PIDX(ob)] = g[0];
        float2 wu = w1;
#pragma unroll
        for (int u = 1; u < 16; u++) {
            sX[PIDX(ob + 16*u)] = cmul(g[u], wu);
            wu = cmul(wu, w1);
        }
    }
    __syncthreads();

    // Stage C: radix-8, S=256, fused with epilogue.
    {
        const int b1 = idx, b2 = 255 - idx;
        float2 A[8], Bv[8];
#pragma unroll
        for (int u = 0; u < 8; u++) A[u]  = sX[PIDX(b1 + 256*u)];
#pragma unroll
        for (int u = 0; u < 8; u++) Bv[u] = sX[PIDX(b2 + 256*u)];
        r8_bfly(A);
        r8_bfly(Bv);
        const float sgn = (MODE == 1) ? -1.0f : 1.0f;
        float4* out4 = (float4*)(out + base);
#pragma unroll
        for (int u = 0; u < 4; u++) {
            float2 z1 = A[u], z2 = Bv[7-u];
            out4[b1 + 256*u] = make_float4(z1.x, sgn*z2.y, z1.y, sgn*z2.x);
            z1 = Bv[u]; z2 = A[7-u];
            out4[b2 + 256*u] = make_float4(z1.x, sgn*z2.y, z1.y, sgn*z2.x);
        }
    }
}

// ---------------------------------------------------------------------------
// Single-batch transpose R x C -> C x R: 64x64 tiles, 256 threads, float4.
// ---------------------------------------------------------------------------
__global__ __launch_bounds__(256)
void transpose_kernel(const float* __restrict__ in, float* __restrict__ out,
                      int R, int C) {
    __shared__ float tile[64][65];
    const int tx = threadIdx.x & 15;
    const int ty = threadIdx.x >> 4;
    const int c0 = blockIdx.x * 64;
    const int r0 = blockIdx.y * 64;

#pragma unroll
    for (int k = 0; k < 4; k++) {
        const int r = ty + 16*k;
        const float4 v = *(const float4*)(in + (size_t)(r0 + r)*C + (c0 + 4*tx));
        tile[r][4*tx+0] = v.x;
        tile[r][4*tx+1] = v.y;
        tile[r][4*tx+2] = v.z;
        tile[r][4*tx+3] = v.w;
    }
    __syncthreads();
#pragma unroll
    for (int k = 0; k < 4; k++) {
        const int r = ty + 16*k;
        float4 v;
        v.x = tile[4*tx+0][r];
        v.y = tile[4*tx+1][r];
        v.z = tile[4*tx+2][r];
        v.w = tile[4*tx+3][r];
        *(float4*)(out + (size_t)(c0 + r)*R + (r0 + 4*tx)) = v;
    }
}

// One-time host resources (handles only; launched work is identical per call).
static cudaStream_t g_s1;
static cudaEvent_t  g_e_fork, g_e_join;
static bool         g_init_done = false;

static void ensure_init() {
    if (!g_init_done) {
        cudaStreamCreateWithFlags(&g_s1, cudaStreamNonBlocking);
        cudaEventCreateWithFlags(&g_e_fork, cudaEventDisableTiming);
        cudaEventCreateWithFlags(&g_e_join, cudaEventDisableTiming);
        g_init_done = true;
    }
}

extern "C" void kernel_launch(void* const* d_in, const int* in_sizes, int n_in,
                              void* d_out, int out_size) {
    const float*  x     = (const float*)d_in[0];
    const float2* expkM = (const float2*)d_in[1];
    const float2* expkN = (const float2*)d_in[2];
    const int M = in_sizes[1] / 2;            // 4096
    const int N = in_sizes[2] / 2;            // 4096
    float* out = (float*)d_out;

    ensure_init();

    float* scratch = nullptr;
    cudaGetSymbolAddress((void**)&scratch, g_scratch);

    const size_t be = (size_t)M * (size_t)N;  // elements per batch
    dim3 tgrid(N / 64, M / 64), tblk(256);

    // ---- batch 0 pipeline on stream 0 (the capturing stream) ----
    dct_fft_kernel<1><<<M, 128, 0, 0>>>(x, expkN, scratch);

    // Fork: batch 1 starts after batch 0's first FFT.
    cudaEventRecord(g_e_fork, 0);
    cudaStreamWaitEvent(g_s1, g_e_fork, 0);

    // batch 1 pipeline on s1
    dct_fft_kernel<1><<<M, 128, 0, g_s1>>>(x + be, expkN, scratch + be);
    transpose_kernel<<<tgrid, tblk, 0, g_s1>>>(scratch + be, out + be, M, N);
    dct_fft_kernel<0><<<N, 128, 0, g_s1>>>(out + be, expkM, scratch + be);
    transpose_kernel<<<tgrid, tblk, 0, g_s1>>>(scratch + be, out + be, N, M);
    cudaEventRecord(g_e_join, g_s1);

    // rest of batch 0 pipeline on stream 0
    transpose_kernel<<<tgrid, tblk, 0, 0>>>(scratch, out, M, N);
    dct_fft_kernel<0><<<N, 128, 0, 0>>>(out, expkM, scratch);
    transpose_kernel<<<tgrid, tblk, 0, 0>>>(scratch, out, N, M);

    // Join: stream 0 (capture stream) waits for batch 1 completion.
    cudaStreamWaitEvent(0, g_e_join, 0);
}

// round 12
// speedup vs baseline: 1.1981x; 1.1981x over previous
#include <cuda_runtime.h>
#include <math.h>

// Scratch: one full-size intermediate buffer (B*M*N floats = 134 MB).
#define SCRATCH_ELEMS (2ull * 4096ull * 4096ull)
__device__ float g_scratch[SCRATCH_ELEMS];

// Problem shape fixed: B=2, M=N=4096. Real-packed FFT length = 2048.
#define NN 4096
#define HH 2048

// ---- packed f32x2 complex add/sub (sm_103a) ----
__device__ __forceinline__ float2 cadd(float2 a, float2 b){
    unsigned long long ua, ub, ur;
    asm("mov.b64 %0, {%1,%2};" : "=l"(ua) : "f"(a.x), "f"(a.y));
    asm("mov.b64 %0, {%1,%2};" : "=l"(ub) : "f"(b.x), "f"(b.y));
    asm("add.rn.f32x2 %0, %1, %2;" : "=l"(ur) : "l"(ua), "l"(ub));
    float2 r;
    asm("mov.b64 {%0,%1}, %2;" : "=f"(r.x), "=f"(r.y) : "l"(ur));
    return r;
}
__device__ __forceinline__ float2 csub(float2 a, float2 b){
    unsigned long long ua, ub, ur;
    asm("mov.b64 %0, {%1,%2};" : "=l"(ua) : "f"(a.x), "f"(a.y));
    asm("mov.b64 %0, {%1,%2};" : "=l"(ub) : "f"(b.x), "f"(b.y));
    asm("sub.rn.f32x2 %0, %1, %2;" : "=l"(ur) : "l"(ua), "l"(ub));
    float2 r;
    asm("mov.b64 {%0,%1}, %2;" : "=f"(r.x), "=f"(r.y) : "l"(ur));
    return r;
}
__device__ __forceinline__ float2 cmul(float2 a, float2 b){
    return make_float2(fmaf(a.x, b.x, -a.y*b.y), fmaf(a.x, b.y, a.y*b.x));
}
__device__ __forceinline__ float2 mulip(float2 a){ return make_float2(-a.y, a.x); }  // * (+i)

// Pad one float2 every 16.
#define PIDX(a) ((a) + ((a) >> 4))
#define PBUF (HH + (HH >> 4))   // 2176 float2

// ---- 16-point inverse DFT in registers ----
__device__ __forceinline__ void r16_bfly(float2 g[16]) {
    const float C8 = 0.70710678118654752f;
    const float2 W1 = make_float2( 0.92387953251128674f,  0.38268343236508978f);
    const float2 W2 = make_float2( C8,  C8);
    const float2 W3 = make_float2( 0.38268343236508978f,  0.92387953251128674f);
    const float2 W6 = make_float2(-C8,  C8);
    const float2 W9 = make_float2(-0.92387953251128674f, -0.38268343236508978f);
    float2 c[16];
#pragma unroll
    for (int t0 = 0; t0 < 4; t0++) {
        float2 x0 = g[t0], x1 = g[t0+4], x2 = g[t0+8], x3 = g[t0+12];
        float2 s02 = cadd(x0,x2), d02 = csub(x0,x2);
        float2 s13 = cadd(x1,x3), d13 = csub(x1,x3);
        float2 id13 = mulip(d13);
        c[t0*4+0] = cadd(s02,s13);
        c[t0*4+1] = cadd(d02,id13);
        c[t0*4+2] = csub(s02,s13);
        c[t0*4+3] = csub(d02,id13);
    }
    c[5]  = cmul(c[5],  W1);
    c[6]  = cmul(c[6],  W2);
    c[7]  = cmul(c[7],  W3);
    c[9]  = cmul(c[9],  W2);
    c[10] = mulip(c[10]);
    c[11] = cmul(c[11], W6);
    c[13] = cmul(c[13], W3);
    c[14] = cmul(c[14], W6);
    c[15] = cmul(c[15], W9);
#pragma unroll
    for (int u0 = 0; u0 < 4; u0++) {
        float2 x0 = c[u0], x1 = c[4+u0], x2 = c[8+u0], x3 = c[12+u0];
        float2 s02 = cadd(x0,x2), d02 = csub(x0,x2);
        float2 s13 = cadd(x1,x3), d13 = csub(x1,x3);
        float2 id13 = mulip(d13);
        g[u0]    = cadd(s02,s13);
        g[u0+4]  = cadd(d02,id13);
        g[u0+8]  = csub(s02,s13);
        g[u0+12] = csub(d02,id13);
    }
}

// ---- 8-point inverse DFT in registers (a[u] -> B_u) ----
__device__ __forceinline__ void r8_bfly(float2 a[8]) {
    const float C8 = 0.70710678118654752f;
    float2 e0 = cadd(a[0],a[4]), e1 = cadd(a[1],a[5]);
    float2 e2 = cadd(a[2],a[6]), e3 = cadd(a[3],a[7]);
    float2 o0 = csub(a[0],a[4]), o1 = csub(a[1],a[5]);
    float2 o2 = csub(a[2],a[6]), o3 = csub(a[3],a[7]);
    o1 = make_float2(C8*(o1.x - o1.y),  C8*(o1.x + o1.y));
    o2 = mulip(o2);
    o3 = make_float2(-C8*(o3.x + o3.y), C8*(o3.x - o3.y));
    float2 t0 = cadd(e0,e2), t1 = csub(e0,e2);
    float2 t2 = cadd(e1,e3), t3 = csub(e1,e3);
    float2 it3 = mulip(t3);
    float2 u0 = cadd(o0,o2), u1 = csub(o0,o2);
    float2 u2 = cadd(o1,o3), u3 = csub(o1,o3);
    float2 iu3 = mulip(u3);
    a[0] = cadd(t0,t2);  a[4] = csub(t0,t2);
    a[2] = cadd(t1,it3); a[6] = csub(t1,it3);
    a[1] = cadd(u0,u2);  a[5] = csub(u0,u2);
    a[3] = cadd(u1,iu3); a[7] = csub(u1,iu3);
}

// ---------------------------------------------------------------------------
// Row FFT kernel: Makhoul pre-twiddle -> real-packed G (2048) -> radix
// 16/16/8 Stockham inverse FFT -> de-interleave epilogue. 128 thr, 1 row/CTA.
// MODE 0 = IDCT-II inverse, MODE 1 = IDXST.
// expk[j] loaded (parallel LDGs, MLP); expk[j+HH] = expk[j]*e^{i pi/4}
// derived with one INDEPENDENT cmul (no loop-carried chain).
// ---------------------------------------------------------------------------
template <int MODE>
__global__ __launch_bounds__(128, 4)
void dct_fft_kernel(const float* __restrict__ in,
                    const float2* __restrict__ expk,
                    float* __restrict__ out) {
    __shared__ __align__(16) float2 sX[PBUF];
    __shared__ __align__(16) float2 sY[PBUF];
    float* xs = (float*)sX;

    const int idx = threadIdx.x;
    const size_t base = (size_t)blockIdx.x * (size_t)NN;

    {
        const float4* in4 = (const float4*)(in + base);
        float4* xs4 = (float4*)xs;
#pragma unroll
        for (int i = idx; i < NN/4; i += 128) xs4[i] = in4[i];
    }
    __syncthreads();

    // Stage A: prologue + radix-16 + twiddle, write sY.
    {
        float2 g[16];
        const float2 E32 = make_float2(0.98078528040323044f, 0.19509032201612827f);   // e^{2pi i/32}
        const float2 PI4 = make_float2(0.70710678118654752f, 0.70710678118654752f);   // e^{i pi/4}
        float sn, cs;
        __sincosf((float)(2.0*M_PI/4096.0) * (float)idx, &sn, &cs);
        float2 w = make_float2(cs, sn);
#pragma unroll
        for (int t = 0; t < 16; t++) {
            const int j = idx + 128*t;
            float Xa0, Xb0, Xa1, Xb1;
            if (MODE == 0) {
                Xa0 = xs[j];
                Xb0 = (j == 0) ? 0.0f : xs[NN - j];
                Xa1 = xs[j + HH];
                Xb1 = xs[(j == 0) ? HH : (HH - j)];
            } else {
                Xa0 = (j == 0) ? 0.0f : xs[NN - j];
                Xb0 = (j == 0) ? 0.0f : xs[j];
                Xa1 = xs[(j == 0) ? HH : (HH - j)];
                Xb1 = xs[j + HH];
            }
            const float2 ea = expk[j];
            const float2 eb = cmul(ea, PI4);   // expk[j + HH], independent cmul
            float2 V0 = make_float2(0.5f*(Xa0*ea.x + Xb0*ea.y),
                                    0.5f*(Xa0*ea.y - Xb0*ea.x));
            float2 V1 = make_float2(0.5f*(Xa1*eb.x + Xb1*eb.y),
                                    0.5f*(Xa1*eb.y - Xb1*eb.x));
            float2 S = cadd(V0, V1);
            float2 D = csub(V0, V1);
            float2 wd = cmul(w, D);
            g[t] = make_float2(S.x - wd.y, S.y + wd.x);
            w = cmul(w, E32);
        }
        r16_bfly(g);
        __sincosf((float)(2.0*M_PI/2048.0) * (float)idx, &sn, &cs);
        const float2 w1 = make_float2(cs, sn);
        sY[PIDX(16*idx)] = g[0];
        float2 wu = w1;
#pragma unroll
        for (int u = 1; u < 16; u++) {
            sY[PIDX(16*idx + u)] = cmul(g[u], wu);
            wu = cmul(wu, w1);
        }
    }
    __syncthreads();

    // Stage B: radix-16, S=16.
    {
        float2 g[16];
#pragma unroll
        for (int t = 0; t < 16; t++) g[t] = sY[PIDX(idx + 128*t)];
        r16_bfly(g);
        const int p = idx >> 4, j = idx & 15;
        float sn, cs;
        __sincosf((float)(2.0*M_PI/128.0) * (float)p, &sn, &cs);
        const float2 w1 = make_float2(cs, sn);
        const int ob = j + 256*p;
        sX[PIDX(ob)] = g[0];
        float2 wu = w1;
#pragma unroll
        for (int u = 1; u < 16; u++) {
            sX[PIDX(ob + 16*u)] = cmul(g[u], wu);
            wu = cmul(wu, w1);
        }
    }
    __syncthreads();

    // Stage C: radix-8, S=256, fused with epilogue.
    {
        const int b1 = idx, b2 = 255 - idx;
        float2 A[8], Bv[8];
#pragma unroll
        for (int u = 0; u < 8; u++) A[u]  = sX[PIDX(b1 + 256*u)];
#pragma unroll
        for (int u = 0; u < 8; u++) Bv[u] = sX[PIDX(b2 + 256*u)];
        r8_bfly(A);
        r8_bfly(Bv);
        const float sgn = (MODE == 1) ? -1.0f : 1.0f;
        float4* out4 = (float4*)(out + base);
#pragma unroll
        for (int u = 0; u < 4; u++) {
            float2 z1 = A[u], z2 = Bv[7-u];
            out4[b1 + 256*u] = make_float4(z1.x, sgn*z2.y, z1.y, sgn*z2.x);
            z1 = Bv[u]; z2 = A[7-u];
            out4[b2 + 256*u] = make_float4(z1.x, sgn*z2.y, z1.y, sgn*z2.x);
        }
    }
}

// ---------------------------------------------------------------------------
// Single-batch transpose R x C -> C x R: 64x64 tiles, 256 threads, float4.
// ---------------------------------------------------------------------------
__global__ __launch_bounds__(256)
void transpose_kernel(const float* __restrict__ in, float* __restrict__ out,
                      int R, int C) {
    __shared__ float tile[64][65];
    const int tx = threadIdx.x & 15;
    const int ty = threadIdx.x >> 4;
    const int c0 = blockIdx.x * 64;
    const int r0 = blockIdx.y * 64;

#pragma unroll
    for (int k = 0; k < 4; k++) {
        const int r = ty + 16*k;
        const float4 v = *(const float4*)(in + (size_t)(r0 + r)*C + (c0 + 4*tx));
        tile[r][4*tx+0] = v.x;
        tile[r][4*tx+1] = v.y;
        tile[r][4*tx+2] = v.z;
        tile[r][4*tx+3] = v.w;
    }
    __syncthreads();
#pragma unroll
    for (int k = 0; k < 4; k++) {
        const int r = ty + 16*k;
        float4 v;
        v.x = tile[4*tx+0][r];
        v.y = tile[4*tx+1][r];
        v.z = tile[4*tx+2][r];
        v.w = tile[4*tx+3][r];
        *(float4*)(out + (size_t)(c0 + r)*R + (r0 + 4*tx)) = v;
    }
}

// One-time host resources (handles only; launched work is identical per call).
static cudaStream_t g_s1;
static cudaEvent_t  g_e_fork, g_e_join;
static bool         g_init_done = false;

static void ensure_init() {
    if (!g_init_done) {
        cudaStreamCreateWithFlags(&g_s1, cudaStreamNonBlocking);
        cudaEventCreateWithFlags(&g_e_fork, cudaEventDisableTiming);
        cudaEventCreateWithFlags(&g_e_join, cudaEventDisableTiming);
        g_init_done = true;
    }
}

extern "C" void kernel_launch(void* const* d_in, const int* in_sizes, int n_in,
                              void* d_out, int out_size) {
    const float*  x     = (const float*)d_in[0];
    const float2* expkM = (const float2*)d_in[1];
    const float2* expkN = (const float2*)d_in[2];
    const int M = in_sizes[1] / 2;            // 4096
    const int N = in_sizes[2] / 2;            // 4096
    float* out = (float*)d_out;

    ensure_init();

    float* scratch = nullptr;
    cudaGetSymbolAddress((void**)&scratch, g_scratch);

    const size_t be = (size_t)M * (size_t)N;  // elements per batch
    dim3 tgrid(N / 64, M / 64), tblk(256);

    // ---- batch 0 pipeline on stream 0 (the capturing stream) ----
    dct_fft_kernel<1><<<M, 128, 0, 0>>>(x, expkN, scratch);

    // Fork: batch 1 starts after batch 0's first FFT.
    cudaEventRecord(g_e_fork, 0);
    cudaStreamWaitEvent(g_s1, g_e_fork, 0);

    // batch 1 pipeline on s1
    dct_fft_kernel<1><<<M, 128, 0, g_s1>>>(x + be, expkN, scratch + be);
    transpose_kernel<<<tgrid, tblk, 0, g_s1>>>(scratch + be, out + be, M, N);
    dct_fft_kernel<0><<<N, 128, 0, g_s1>>>(out + be, expkM, scratch + be);
    transpose_kernel<<<tgrid, tblk, 0, g_s1>>>(scratch + be, out + be, N, M);
    cudaEventRecord(g_e_join, g_s1);

    // rest of batch 0 pipeline on stream 0
    transpose_kernel<<<tgrid, tblk, 0, 0>>>(scratch, out, M, N);
    dct_fft_kernel<0><<<N, 128, 0, 0>>>(out, expkM, scratch);
    transpose_kernel<<<tgrid, tblk, 0, 0>>>(scratch, out, N, M);

    // Join: stream 0 (capture stream) waits for batch 1 completion.
    cudaStreamWaitEvent(0, g_e_join, 0);
}